// round 6
// baseline (speedup 1.0000x reference)
#include <cuda_runtime.h>

// ---------------------------------------------------------------------------
// RestorationLoss: 1 - SSIM(x,y) + MSE(x,y), single fused kernel.
//   * separable 11-tap Gaussian on fields s=x+y, d=x-y and their squares
//   * ALL conv math as scalar FFMA with IMMEDIATE weights (rt_SMSP=1: 2x tput)
//   * h-pass: 8 outputs/thread, 4 own float4 loads/image + shfl endpoints
//   * v-pass: 8 outputs/thread, float4 LDS of interleaved (s,d,ss,dd)
//   * 4 blocks/SM; deterministic fixed-point atomic reduction
// ---------------------------------------------------------------------------

#define IMG     512
#define TW      32
#define TH      64
#define HALO    5
#define LH      74                 // TH + 2*HALO
#define HSTR    66                 // ull row stride (32 interleaved pairs + pad)
#define HUNITS  (LH*4)             // 296 h-pass work units
#define NBX     (IMG/TW)           // 16
#define NBY     (IMG/TH)           // 8
#define NPL     48
#define NBLOCKS (NBX*NBY*NPL)      // 6144
#define NPIX    (16.0*3.0*512.0*512.0)
#define FXS     268435456.0        // 2^28

#define C1f 1.0e-4f
#define C2f 9.0e-4f

typedef unsigned long long ull;

// compile-time gaussian weights -> FFMA immediates after unrolling
static __host__ __device__ constexpr float GWF(int k) {
    constexpr float g[11] = {
        0.00102838f, 0.00759876f, 0.03600077f, 0.10936069f, 0.21300554f,
        0.26601172f,
        0.21300554f, 0.10936069f, 0.03600077f, 0.00759876f, 0.00102838f };
    return g[k];
}

__device__ ull g_acc[2] = {0ull, 0ull};
__device__ unsigned g_count = 0u;

static __device__ __forceinline__ ull pack2(float lo, float hi) {
    ull r; asm("mov.b64 %0, {%1,%2};" : "=l"(r) : "f"(lo), "f"(hi));
    return r;
}
static __device__ __forceinline__ float2 unpack2(ull v) {
    float2 r; asm("mov.b64 {%0,%1}, %2;" : "=f"(r.x), "=f"(r.y) : "l"(v));
    return r;
}

__global__ __launch_bounds__(256, 4)
void loss_kernel(const float* __restrict__ x, const float* __restrict__ y,
                 float* __restrict__ out)
{
    __shared__ ull  h[LH * HSTR];      // col c -> float4 (s,d,ss,dd) at 2c
    __shared__ float red[16];
    __shared__ int  s_last;

    const int tid   = threadIdx.x;
    const int bx    = blockIdx.x;
    const int by    = blockIdx.y;
    const int plane = blockIdx.z;
    const int base  = bx * TW;
    const int r0    = by * TH - HALO;

    const float* __restrict__ xp = x + (size_t)plane * (IMG * IMG);
    const float* __restrict__ yp = y + (size_t)plane * (IMG * IMG);

    // ---- horizontal pass: 8 outputs/unit ----
    float mse_acc = 0.f;
    #pragma unroll
    for (int iter = 0; iter < 2; iter++) {
        const int u      = iter * 256 + tid;
        const bool valid = (u < HUNITS);
        const int uu     = valid ? u : (HUNITS - 1);
        const int r      = uu >> 2;
        const int q      = uu & 3;
        const int gr     = r0 + r;
        const bool rowok = ((unsigned)gr < IMG);
        const int c0c    = base + 8 * q;
        const float* xrow = xp + gr * IMG;
        const float* yrow = yp + gr * IMG;

        // own + adjacent loads: cols [c0c-4, c0c+12)
        float4 X[4], Y[4];
        #pragma unroll
        for (int m = 0; m < 4; m++) {
            const int col = c0c - 4 + 4 * m;
            const bool ok = rowok & ((unsigned)col < IMG);
            X[m] = ok ? __ldg((const float4*)(xrow + col)) : make_float4(0.f,0.f,0.f,0.f);
            Y[m] = ok ? __ldg((const float4*)(yrow + col)) : make_float4(0.f,0.f,0.f,0.f);
        }
        // edge-quad extras (window endpoints outside warp neighbors)
        float ex = 0.f, ey = 0.f, fxe = 0.f, fye = 0.f;
        if (q == 0) {
            const int col = base - 8;
            if (rowok & (col >= 0)) {
                ex = __ldg((const float4*)(xrow + col)).w;
                ey = __ldg((const float4*)(yrow + col)).w;
            }
        }
        if (q == 3) {
            const int col = c0c + 12;
            if (rowok & ((unsigned)col < IMG)) {
                fxe = __ldg((const float4*)(xrow + col)).x;
                fye = __ldg((const float4*)(yrow + col)).x;
            }
        }

        // window s/d[0..17] <-> cols c0c-5 .. c0c+12
        float ws[18], wd[18];
        #pragma unroll
        for (int m = 0; m < 4; m++) {
            const float* fxp = (const float*)&X[m];
            const float* fyp = (const float*)&Y[m];
            #pragma unroll
            for (int e = 0; e < 4; e++) {
                ws[1 + 4*m + e] = fxp[e] + fyp[e];
                wd[1 + 4*m + e] = fxp[e] - fyp[e];
            }
        }
        {
            ull wl = __shfl_up_sync(0xffffffffu, pack2(ws[8], wd[8]), 1);
            ull wr = __shfl_down_sync(0xffffffffu, pack2(ws[9], wd[9]), 1);
            float2 l = unpack2(wl), rr = unpack2(wr);
            if (q == 0) { l.x = ex + ey;  l.y = ex - ey; }
            if (q == 3) { rr.x = fxe + fye; rr.y = fxe - fye; }
            ws[0] = l.x;  wd[0] = l.y;
            ws[17] = rr.x; wd[17] = rr.y;
        }

        const bool mrowok = valid & (r >= HALO) & (r < HALO + TH) & rowok;
        if (mrowok) {
            #pragma unroll
            for (int t = 5; t <= 12; t++)
                mse_acc = fmaf(wd[t], wd[t], mse_acc);
        }

        // two groups of 4 outputs to cap live registers
        ull* hrow = h + r * HSTR;
        #pragma unroll
        for (int g = 0; g < 2; g++) {
            float as[4] = {0,0,0,0}, ad[4] = {0,0,0,0};
            float af[4] = {0,0,0,0}, ag[4] = {0,0,0,0};
            #pragma unroll
            for (int t = 4*g; t < 4*g + 14; t++) {
                float sv = ws[t], dv = wd[t];
                float s2 = sv * sv, d2 = dv * dv;
                #pragma unroll
                for (int o = 0; o < 4; o++) {
                    const int k = t - (4*g + o);
                    if (k >= 0 && k <= 10) {
                        as[o] = fmaf(sv, GWF(k), as[o]);
                        ad[o] = fmaf(dv, GWF(k), ad[o]);
                        af[o] = fmaf(s2, GWF(k), af[o]);
                        ag[o] = fmaf(d2, GWF(k), ag[o]);
                    }
                }
            }
            if (valid) {
                #pragma unroll
                for (int o = 0; o < 4; o++) {
                    *((float4*)(hrow + 2 * (8*q + 4*g + o))) =
                        make_float4(as[o], ad[o], af[o], ag[o]);
                }
            }
        }
    }
    __syncthreads();

    // ---- vertical pass: 1 column x 8 consecutive rows per thread ----
    const int c  = tid & 31;
    const int rb = (tid >> 5) * 8;     // 0,8,...,56

    float bs[8] = {0,0,0,0,0,0,0,0}, bd[8] = {0,0,0,0,0,0,0,0};
    float bf[8] = {0,0,0,0,0,0,0,0}, bg[8] = {0,0,0,0,0,0,0,0};
    const ull* vp = h + rb * HSTR + 2 * c;
    #pragma unroll
    for (int j = 0; j < 18; j++) {
        float4 uv = *((const float4*)(vp + j * HSTR));
        #pragma unroll
        for (int o = 0; o < 8; o++) {
            const int k = j - o;
            if (k >= 0 && k <= 10) {
                bs[o] = fmaf(uv.x, GWF(k), bs[o]);
                bd[o] = fmaf(uv.y, GWF(k), bd[o]);
                bf[o] = fmaf(uv.z, GWF(k), bf[o]);
                bg[o] = fmaf(uv.w, GWF(k), bg[o]);
            }
        }
    }

    float ssim_acc = 0.f;
    #pragma unroll
    for (int o = 0; o < 8; o++) {
        float mus = bs[o], mud = bd[o];
        float ess = bf[o], edd = bg[o];
        float mus2 = mus * mus;
        float mud2 = mud * mud;
        float mu12   = 0.25f * (mus2 - mud2);
        float musum  = 0.5f  * (mus2 + mud2);
        float sig12  = 0.25f * (ess - edd) - mu12;
        float sigsum = 0.5f  * (ess + edd) - musum;
        float num = (2.f * mu12 + C1f) * (2.f * sig12 + C2f);
        float den = (musum + C1f) * (sigsum + C2f);
        ssim_acc += __fdividef(num, den);
    }

    // ---- block reduction -> deterministic fixed-point atomics ----
    #pragma unroll
    for (int off = 16; off > 0; off >>= 1) {
        ssim_acc += __shfl_down_sync(0xffffffffu, ssim_acc, off);
        mse_acc  += __shfl_down_sync(0xffffffffu, mse_acc,  off);
    }
    if ((tid & 31) == 0) {
        red[tid >> 5]       = ssim_acc;
        red[8 + (tid >> 5)] = mse_acc;
    }
    __syncthreads();
    if (tid == 0) {
        float ss = 0.f, mm = 0.f;
        #pragma unroll
        for (int w2 = 0; w2 < 8; w2++) { ss += red[w2]; mm += red[8 + w2]; }
        atomicAdd(&g_acc[0], (ull)__double2ll_rn((double)ss * FXS));
        atomicAdd(&g_acc[1], (ull)__double2ll_rn((double)mm * FXS));
        __threadfence();
        unsigned t = atomicAdd(&g_count, 1u);
        s_last = (t == NBLOCKS - 1);
    }
    __syncthreads();

    // ---- last block finalizes and resets for next graph replay ----
    if (s_last && tid == 0) {
        __threadfence();
        ull a0  = atomicExch(&g_acc[0], 0ull);
        ull a1v = atomicExch(&g_acc[1], 0ull);
        atomicExch(&g_count, 0u);
        double inv = 1.0 / (NPIX * FXS);
        double ss = (double)(long long)a0 * inv;
        double mm = (double)(long long)a1v * inv;
        out[0] = (float)(1.0 - ss + mm);
    }
}

extern "C" void kernel_launch(void* const* d_in, const int* in_sizes, int n_in,
                              void* d_out, int out_size)
{
    const float* x = (const float*)d_in[0];
    const float* y = (const float*)d_in[1];
    float* out = (float*)d_out;

    dim3 grid(NBX, NBY, NPL);   // (16, 8, 48) = 6144 blocks
    loss_kernel<<<grid, 256>>>(x, y, out);
}

// round 7
// speedup vs baseline: 1.0962x; 1.0962x over previous
#include <cuda_runtime.h>

// ---------------------------------------------------------------------------
// RestorationLoss: 1 - SSIM(x,y) + MSE(x,y), single fused kernel.
//   * separable 11-tap Gaussian; packed f32x2 fields (s,d),(s^2,d^2) (FFMA2)
//   * h-pass: 8 outputs/thread, 4 own float4 loads + shfl for window endpoints
//   * v-pass: 11 outputs/thread (21/11 re-read ratio)
//   * SSIM divisions batched 4-at-a-time -> 1 MUFU.RCP per 4 pixels
//   * deterministic fixed-point atomic reduction + last-block finalize/reset
// ---------------------------------------------------------------------------

#define IMG     512
#define TW      32
#define TH      88
#define HALO    5
#define LH      98                 // TH + 2*HALO
#define HSTR    66                 // ull row stride (32 interleaved pairs + pad)
#define HUNITS  (LH*4)             // 392 h-pass work units
#define NBX     (IMG/TW)           // 16
#define NBY     6                  // ceil(512/88)
#define NPL     48
#define NBLOCKS (NBX*NBY*NPL)      // 4608
#define NPIX    (16.0*3.0*512.0*512.0)
#define FXS     268435456.0        // 2^28

#define C1f 1.0e-4f
#define C2f 9.0e-4f

typedef unsigned long long ull;

__constant__ float2 GW2[6] = {
    {0.00102838f, 0.00102838f},
    {0.00759876f, 0.00759876f},
    {0.03600077f, 0.03600077f},
    {0.10936069f, 0.10936069f},
    {0.21300554f, 0.21300554f},
    {0.26601172f, 0.26601172f}
};

__device__ ull g_acc[2] = {0ull, 0ull};
__device__ unsigned g_count = 0u;

static __device__ __forceinline__ ull fma2(ull a, ull b, ull c) {
    ull r; asm("fma.rn.f32x2 %0, %1, %2, %3;" : "=l"(r) : "l"(a), "l"(b), "l"(c));
    return r;
}
static __device__ __forceinline__ ull mul2(ull a, ull b) {
    ull r; asm("mul.rn.f32x2 %0, %1, %2;" : "=l"(r) : "l"(a), "l"(b));
    return r;
}
static __device__ __forceinline__ ull pack2(float lo, float hi) {
    ull r; asm("mov.b64 %0, {%1,%2};" : "=l"(r) : "f"(lo), "f"(hi));
    return r;
}
static __device__ __forceinline__ float2 unpack2(ull v) {
    float2 r; asm("mov.b64 {%0,%1}, %2;" : "=f"(r.x), "=f"(r.y) : "l"(v));
    return r;
}
static __device__ __forceinline__ float frcp(float a) {
    float r; asm("rcp.approx.ftz.f32 %0, %1;" : "=f"(r) : "f"(a));
    return r;
}

__global__ __launch_bounds__(256, 3)
void loss_kernel(const float* __restrict__ x, const float* __restrict__ y,
                 float* __restrict__ out)
{
    __shared__ ull  h[LH * HSTR];      // interleaved (h1,h2): col c -> 2c, 2c+1
    __shared__ float red[16];
    __shared__ int  s_last;

    const int tid   = threadIdx.x;
    const int bx    = blockIdx.x;
    const int by    = blockIdx.y;
    const int plane = blockIdx.z;
    const int base  = bx * TW;
    const int r0    = by * TH - HALO;

    const float* __restrict__ xp = x + (size_t)plane * (IMG * IMG);
    const float* __restrict__ yp = y + (size_t)plane * (IMG * IMG);

    ull gw[6];
    #pragma unroll
    for (int k = 0; k < 6; k++) gw[k] = ((const ull*)GW2)[k];
    #define WK(k) gw[(k) <= 5 ? (k) : 10 - (k)]

    // ---- horizontal pass: 8 outputs/unit, window endpoints via shfl ----
    ull mse2 = 0ull;                  // packed (junk, sum d^2)
    for (int iter = 0; iter < 2; iter++) {
        const int u     = iter * 256 + tid;
        const bool valid = (u < HUNITS);
        const int uu    = valid ? u : (HUNITS - 1);
        const int r     = uu >> 2;
        const int q     = uu & 3;
        const int gr    = r0 + r;
        const bool rowok = ((unsigned)gr < IMG);
        const int c0c   = base + 8 * q;
        const float* xrow = xp + gr * IMG;
        const float* yrow = yp + gr * IMG;

        float4 X[4], Y[4];
        #pragma unroll
        for (int m = 0; m < 4; m++) {
            const int col = c0c - 4 + 4 * m;
            const bool ok = rowok & ((unsigned)col < IMG);
            X[m] = ok ? __ldg((const float4*)(xrow + col)) : make_float4(0.f,0.f,0.f,0.f);
            Y[m] = ok ? __ldg((const float4*)(yrow + col)) : make_float4(0.f,0.f,0.f,0.f);
        }
        float ex = 0.f, ey = 0.f, fxe = 0.f, fye = 0.f;
        if (q == 0) {
            const int col = base - 8;
            if (rowok & (col >= 0)) {
                ex = __ldg((const float4*)(xrow + col)).w;
                ey = __ldg((const float4*)(yrow + col)).w;
            }
        }
        if (q == 3) {
            const int col = c0c + 12;
            if (rowok & ((unsigned)col < IMG)) {
                fxe = __ldg((const float4*)(xrow + col)).x;
                fye = __ldg((const float4*)(yrow + col)).x;
            }
        }

        ull w[18];
        #pragma unroll
        for (int m = 0; m < 4; m++) {
            const float* fxp = (const float*)&X[m];
            const float* fyp = (const float*)&Y[m];
            #pragma unroll
            for (int e = 0; e < 4; e++)
                w[1 + 4*m + e] = pack2(fxp[e] + fyp[e], fxp[e] - fyp[e]);
        }
        ull wl = __shfl_up_sync(0xffffffffu, w[8], 1);
        ull wr = __shfl_down_sync(0xffffffffu, w[9], 1);
        if (q == 0) wl = pack2(ex + ey, ex - ey);
        if (q == 3) wr = pack2(fxe + fye, fxe - fye);
        w[0]  = wl;
        w[17] = wr;

        const bool mrowok = valid & (r >= HALO) & (r < HALO + TH) & (gr < IMG);

        ull a1[8] = {0,0,0,0,0,0,0,0};
        ull a2[8] = {0,0,0,0,0,0,0,0};
        #pragma unroll
        for (int t = 0; t < 18; t++) {
            ull v  = w[t];
            ull v2 = mul2(v, v);
            if (t >= 5 && t <= 12) {
                if (mrowok) mse2 = fma2(v, v, mse2);
            }
            #pragma unroll
            for (int o = 0; o < 8; o++) {
                const int k = t - o;
                if (k >= 0 && k <= 10) {
                    a1[o] = fma2(v,  WK(k), a1[o]);
                    a2[o] = fma2(v2, WK(k), a2[o]);
                }
            }
        }
        if (valid) {
            ull* hrow = h + r * HSTR;
            #pragma unroll
            for (int o = 0; o < 8; o++)
                *((ulonglong2*)(hrow + 2 * (8*q + o))) = make_ulonglong2(a1[o], a2[o]);
        }
    }
    float mse_acc = unpack2(mse2).y;
    __syncthreads();

    // ---- vertical pass: 1 column x 11 consecutive rows per thread ----
    const int c  = tid & 31;
    const int rb = (tid >> 5) * 11;

    ull b1[11] = {0,0,0,0,0,0,0,0,0,0,0};
    ull b2[11] = {0,0,0,0,0,0,0,0,0,0,0};
    const ull* vp = h + rb * HSTR + 2 * c;
    #pragma unroll
    for (int j = 0; j < 21; j++) {
        ulonglong2 u = *((const ulonglong2*)(vp + j * HSTR));
        #pragma unroll
        for (int o = 0; o < 11; o++) {
            const int k = j - o;
            if (k >= 0 && k <= 10) {
                b1[o] = fma2(u.x, WK(k), b1[o]);
                b2[o] = fma2(u.y, WK(k), b2[o]);
            }
        }
    }

    // ---- SSIM epilogue: batch 4 divisions per MUFU.RCP ----
    float ssim_acc = 0.f;
    float Nacc = 0.f, Dacc = 1.f;
    int   cnt = 0;
    #pragma unroll
    for (int o = 0; o < 11; o++) {
        const int gro = by * TH + rb + o;
        if (gro < IMG) {
            float2 m = unpack2(b1[o]);   // (mu_s, mu_d)
            float2 e = unpack2(b2[o]);   // (E[s^2], E[d^2])
            float mus2 = m.x * m.x;
            float mud2 = m.y * m.y;
            float mu12   = 0.25f * (mus2 - mud2);
            float musum  = 0.5f  * (mus2 + mud2);
            float sig12  = 0.25f * (e.x - e.y) - mu12;
            float sigsum = 0.5f  * (e.x + e.y) - musum;
            float num = (2.f * mu12 + C1f) * (2.f * sig12 + C2f);
            float den = (musum + C1f) * (sigsum + C2f);
            // running fraction: Nacc/Dacc += num/den
            Nacc = Nacc * den + num * Dacc;
            Dacc = Dacc * den;
            cnt++;
            if (cnt == 4) {
                ssim_acc = fmaf(Nacc, frcp(Dacc), ssim_acc);
                Nacc = 0.f; Dacc = 1.f; cnt = 0;
            }
        }
    }
    if (cnt > 0)
        ssim_acc = fmaf(Nacc, frcp(Dacc), ssim_acc);

    // ---- block reduction -> deterministic fixed-point atomics ----
    #pragma unroll
    for (int off = 16; off > 0; off >>= 1) {
        ssim_acc += __shfl_down_sync(0xffffffffu, ssim_acc, off);
        mse_acc  += __shfl_down_sync(0xffffffffu, mse_acc,  off);
    }
    if ((tid & 31) == 0) {
        red[tid >> 5]       = ssim_acc;
        red[8 + (tid >> 5)] = mse_acc;
    }
    __syncthreads();
    if (tid == 0) {
        float ss = 0.f, mm = 0.f;
        #pragma unroll
        for (int w2 = 0; w2 < 8; w2++) { ss += red[w2]; mm += red[8 + w2]; }
        atomicAdd(&g_acc[0], (ull)__double2ll_rn((double)ss * FXS));
        atomicAdd(&g_acc[1], (ull)__double2ll_rn((double)mm * FXS));
        __threadfence();
        unsigned t = atomicAdd(&g_count, 1u);
        s_last = (t == NBLOCKS - 1);
    }
    __syncthreads();

    // ---- last block finalizes and resets for next graph replay ----
    if (s_last && tid == 0) {
        __threadfence();
        ull a0  = atomicExch(&g_acc[0], 0ull);
        ull a1v = atomicExch(&g_acc[1], 0ull);
        atomicExch(&g_count, 0u);
        double inv = 1.0 / (NPIX * FXS);
        double ss = (double)(long long)a0 * inv;
        double mm = (double)(long long)a1v * inv;
        out[0] = (float)(1.0 - ss + mm);
    }
}

extern "C" void kernel_launch(void* const* d_in, const int* in_sizes, int n_in,
                              void* d_out, int out_size)
{
    const float* x = (const float*)d_in[0];
    const float* y = (const float*)d_in[1];
    float* out = (float*)d_out;

    dim3 grid(NBX, NBY, NPL);   // (16, 6, 48) = 4608 blocks
    loss_kernel<<<grid, 256>>>(x, y, out);
}

// round 8
// speedup vs baseline: 1.1886x; 1.0842x over previous
#include <cuda_runtime.h>

// ---------------------------------------------------------------------------
// RestorationLoss: 1 - SSIM(x,y) + MSE(x,y), single fused kernel.
//   * separable 11-tap Gaussian; packed f32x2 fields (s,d),(s^2,d^2) (FFMA2)
//   * h-pass: 8 outputs/thread, 4 own float4 loads + shfl for window endpoints
//   * SKEWED h-buffer (col c -> ull 2c + 2(c>>3), row stride 72): conflict-free
//     STS.128 AND LDS.128 (R7 layout was 4-way STS conflicted)
//   * v-pass: 11 outputs/thread; rcp batched 4x
//   * deterministic fixed-point atomic reduction + last-block finalize/reset
// ---------------------------------------------------------------------------

#define IMG     512
#define TW      32
#define TH      88
#define HALO    5
#define LH      98                 // TH + 2*HALO
#define HSTR    72                 // ull row stride (576B == 64 mod 128: CF)
#define HUNITS  (LH*4)             // 392 h-pass work units
#define NBX     (IMG/TW)           // 16
#define NBY     6                  // ceil(512/88)
#define NPL     48
#define NBLOCKS (NBX*NBY*NPL)      // 4608
#define NPIX    (16.0*3.0*512.0*512.0)
#define FXS     268435456.0        // 2^28
#define SMEMB   (LH*HSTR*8)        // 56448 bytes (dynamic)

#define C1f 1.0e-4f
#define C2f 9.0e-4f

typedef unsigned long long ull;

// skewed column placement inside a row (ull units); 16B-aligned for all c
#define SKEW(c) (2*(c) + 2*((c) >> 3))

__constant__ float2 GW2[6] = {
    {0.00102838f, 0.00102838f},
    {0.00759876f, 0.00759876f},
    {0.03600077f, 0.03600077f},
    {0.10936069f, 0.10936069f},
    {0.21300554f, 0.21300554f},
    {0.26601172f, 0.26601172f}
};

__device__ ull g_acc[2] = {0ull, 0ull};
__device__ unsigned g_count = 0u;

static __device__ __forceinline__ ull fma2(ull a, ull b, ull c) {
    ull r; asm("fma.rn.f32x2 %0, %1, %2, %3;" : "=l"(r) : "l"(a), "l"(b), "l"(c));
    return r;
}
static __device__ __forceinline__ ull mul2(ull a, ull b) {
    ull r; asm("mul.rn.f32x2 %0, %1, %2;" : "=l"(r) : "l"(a), "l"(b));
    return r;
}
static __device__ __forceinline__ ull pack2(float lo, float hi) {
    ull r; asm("mov.b64 %0, {%1,%2};" : "=l"(r) : "f"(lo), "f"(hi));
    return r;
}
static __device__ __forceinline__ float2 unpack2(ull v) {
    float2 r; asm("mov.b64 {%0,%1}, %2;" : "=f"(r.x), "=f"(r.y) : "l"(v));
    return r;
}
static __device__ __forceinline__ float frcp(float a) {
    float r; asm("rcp.approx.ftz.f32 %0, %1;" : "=f"(r) : "f"(a));
    return r;
}

__global__ __launch_bounds__(256, 3)
void loss_kernel(const float* __restrict__ x, const float* __restrict__ y,
                 float* __restrict__ out)
{
    extern __shared__ ull h[];         // [LH][HSTR], skewed columns
    __shared__ float red[16];
    __shared__ int  s_last;

    const int tid   = threadIdx.x;
    const int bx    = blockIdx.x;
    const int by    = blockIdx.y;
    const int plane = blockIdx.z;
    const int base  = bx * TW;
    const int r0    = by * TH - HALO;

    const float* __restrict__ xp = x + (size_t)plane * (IMG * IMG);
    const float* __restrict__ yp = y + (size_t)plane * (IMG * IMG);

    ull gw[6];
    #pragma unroll
    for (int k = 0; k < 6; k++) gw[k] = ((const ull*)GW2)[k];
    #define WK(k) gw[(k) <= 5 ? (k) : 10 - (k)]

    // ---- horizontal pass: 8 outputs/unit, window endpoints via shfl ----
    ull mse2 = 0ull;                  // packed (junk, sum d^2)
    for (int iter = 0; iter < 2; iter++) {
        const int u     = iter * 256 + tid;
        const bool valid = (u < HUNITS);
        const int uu    = valid ? u : (HUNITS - 1);
        const int r     = uu >> 2;
        const int q     = uu & 3;
        const int gr    = r0 + r;
        const bool rowok = ((unsigned)gr < IMG);
        const int c0c   = base + 8 * q;
        const float* xrow = xp + gr * IMG;
        const float* yrow = yp + gr * IMG;

        float4 X[4], Y[4];
        #pragma unroll
        for (int m = 0; m < 4; m++) {
            const int col = c0c - 4 + 4 * m;
            const bool ok = rowok & ((unsigned)col < IMG);
            X[m] = ok ? __ldg((const float4*)(xrow + col)) : make_float4(0.f,0.f,0.f,0.f);
            Y[m] = ok ? __ldg((const float4*)(yrow + col)) : make_float4(0.f,0.f,0.f,0.f);
        }
        float ex = 0.f, ey = 0.f, fxe = 0.f, fye = 0.f;
        if (q == 0) {
            const int col = base - 8;
            if (rowok & (col >= 0)) {
                ex = __ldg((const float4*)(xrow + col)).w;
                ey = __ldg((const float4*)(yrow + col)).w;
            }
        }
        if (q == 3) {
            const int col = c0c + 12;
            if (rowok & ((unsigned)col < IMG)) {
                fxe = __ldg((const float4*)(xrow + col)).x;
                fye = __ldg((const float4*)(yrow + col)).x;
            }
        }

        ull w[18];
        #pragma unroll
        for (int m = 0; m < 4; m++) {
            const float* fxp = (const float*)&X[m];
            const float* fyp = (const float*)&Y[m];
            #pragma unroll
            for (int e = 0; e < 4; e++)
                w[1 + 4*m + e] = pack2(fxp[e] + fyp[e], fxp[e] - fyp[e]);
        }
        ull wl = __shfl_up_sync(0xffffffffu, w[8], 1);
        ull wr = __shfl_down_sync(0xffffffffu, w[9], 1);
        if (q == 0) wl = pack2(ex + ey, ex - ey);
        if (q == 3) wr = pack2(fxe + fye, fxe - fye);
        w[0]  = wl;
        w[17] = wr;

        const bool mrowok = valid & (r >= HALO) & (r < HALO + TH) & (gr < IMG);

        ull a1[8] = {0,0,0,0,0,0,0,0};
        ull a2[8] = {0,0,0,0,0,0,0,0};
        #pragma unroll
        for (int t = 0; t < 18; t++) {
            ull v  = w[t];
            ull v2 = mul2(v, v);
            if (t >= 5 && t <= 12) {
                if (mrowok) mse2 = fma2(v, v, mse2);
            }
            #pragma unroll
            for (int o = 0; o < 8; o++) {
                const int k = t - o;
                if (k >= 0 && k <= 10) {
                    a1[o] = fma2(v,  WK(k), a1[o]);
                    a2[o] = fma2(v2, WK(k), a2[o]);
                }
            }
        }
        if (valid) {
            ull* hrow = h + r * HSTR;
            #pragma unroll
            for (int o = 0; o < 8; o++)
                *((ulonglong2*)(hrow + SKEW(8*q + o))) = make_ulonglong2(a1[o], a2[o]);
        }
    }
    float mse_acc = unpack2(mse2).y;
    __syncthreads();

    // ---- vertical pass: 1 column x 11 consecutive rows per thread ----
    const int c  = tid & 31;
    const int rb = (tid >> 5) * 11;

    ull b1[11] = {0,0,0,0,0,0,0,0,0,0,0};
    ull b2[11] = {0,0,0,0,0,0,0,0,0,0,0};
    const ull* vp = h + rb * HSTR + SKEW(c);
    #pragma unroll
    for (int j = 0; j < 21; j++) {
        ulonglong2 u = *((const ulonglong2*)(vp + j * HSTR));
        #pragma unroll
        for (int o = 0; o < 11; o++) {
            const int k = j - o;
            if (k >= 0 && k <= 10) {
                b1[o] = fma2(u.x, WK(k), b1[o]);
                b2[o] = fma2(u.y, WK(k), b2[o]);
            }
        }
    }

    // ---- SSIM epilogue: batch 4 divisions per MUFU.RCP ----
    float ssim_acc = 0.f;
    float Nacc = 0.f, Dacc = 1.f;
    int   cnt = 0;
    #pragma unroll
    for (int o = 0; o < 11; o++) {
        const int gro = by * TH + rb + o;
        if (gro < IMG) {
            float2 m = unpack2(b1[o]);   // (mu_s, mu_d)
            float2 e = unpack2(b2[o]);   // (E[s^2], E[d^2])
            float mus2 = m.x * m.x;
            float mud2 = m.y * m.y;
            float mu12   = 0.25f * (mus2 - mud2);
            float musum  = 0.5f  * (mus2 + mud2);
            float sig12  = 0.25f * (e.x - e.y) - mu12;
            float sigsum = 0.5f  * (e.x + e.y) - musum;
            float num = (2.f * mu12 + C1f) * (2.f * sig12 + C2f);
            float den = (musum + C1f) * (sigsum + C2f);
            Nacc = Nacc * den + num * Dacc;
            Dacc = Dacc * den;
            cnt++;
            if (cnt == 4) {
                ssim_acc = fmaf(Nacc, frcp(Dacc), ssim_acc);
                Nacc = 0.f; Dacc = 1.f; cnt = 0;
            }
        }
    }
    if (cnt > 0)
        ssim_acc = fmaf(Nacc, frcp(Dacc), ssim_acc);

    // ---- block reduction -> deterministic fixed-point atomics ----
    #pragma unroll
    for (int off = 16; off > 0; off >>= 1) {
        ssim_acc += __shfl_down_sync(0xffffffffu, ssim_acc, off);
        mse_acc  += __shfl_down_sync(0xffffffffu, mse_acc,  off);
    }
    if ((tid & 31) == 0) {
        red[tid >> 5]       = ssim_acc;
        red[8 + (tid >> 5)] = mse_acc;
    }
    __syncthreads();
    if (tid == 0) {
        float ss = 0.f, mm = 0.f;
        #pragma unroll
        for (int w2 = 0; w2 < 8; w2++) { ss += red[w2]; mm += red[8 + w2]; }
        atomicAdd(&g_acc[0], (ull)__double2ll_rn((double)ss * FXS));
        atomicAdd(&g_acc[1], (ull)__double2ll_rn((double)mm * FXS));
        __threadfence();
        unsigned t = atomicAdd(&g_count, 1u);
        s_last = (t == NBLOCKS - 1);
    }
    __syncthreads();

    // ---- last block finalizes and resets for next graph replay ----
    if (s_last && tid == 0) {
        __threadfence();
        ull a0  = atomicExch(&g_acc[0], 0ull);
        ull a1v = atomicExch(&g_acc[1], 0ull);
        atomicExch(&g_count, 0u);
        double inv = 1.0 / (NPIX * FXS);
        double ss = (double)(long long)a0 * inv;
        double mm = (double)(long long)a1v * inv;
        out[0] = (float)(1.0 - ss + mm);
    }
}

extern "C" void kernel_launch(void* const* d_in, const int* in_sizes, int n_in,
                              void* d_out, int out_size)
{
    const float* x = (const float*)d_in[0];
    const float* y = (const float*)d_in[1];
    float* out = (float*)d_out;

    cudaFuncSetAttribute(loss_kernel,
                         cudaFuncAttributeMaxDynamicSharedMemorySize, SMEMB);

    dim3 grid(NBX, NBY, NPL);   // (16, 6, 48) = 4608 blocks
    loss_kernel<<<grid, 256, SMEMB>>>(x, y, out);
}

// round 9
// speedup vs baseline: 1.2524x; 1.0537x over previous
#include <cuda_runtime.h>

// ---------------------------------------------------------------------------
// RestorationLoss: 1 - SSIM(x,y) + MSE(x,y), single fused kernel.
//   * separable 11-tap Gaussian; packed f32x2 fields (s,d),(s^2,d^2) (FFMA2)
//   * h-pass: 8 outputs/thread; HUNITS=384=256+128 -> issue-exact, no ghost
//     units (R8 wasted 23% of h-pass slots on clamped work)
//   * SKEWED h-buffer (col c -> ull 2c + 2(c>>3), stride 72): conflict-free
//   * v-pass: 11 outputs/thread; rcp batched 4x
//   * deterministic fixed-point atomic reduction + last-block finalize/reset
// ---------------------------------------------------------------------------

#define IMG     512
#define TW      32
#define TH      86
#define HALO    5
#define LH      96                 // h rows produced (TH + 2*HALO)
#define LHBUF   98                 // + 2 zeroed guard rows for v-pass overhang
#define HSTR    72                 // ull row stride (576B == 64 mod 128: CF)
#define NBX     (IMG/TW)           // 16
#define NBY     6                  // ceil(512/86)
#define NPL     48
#define NBLOCKS (NBX*NBY*NPL)      // 4608
#define NPIX    (16.0*3.0*512.0*512.0)
#define FXS     268435456.0        // 2^28
#define SMEMB   (LHBUF*HSTR*8)     // 56448 bytes (dynamic)

#define C1f 1.0e-4f
#define C2f 9.0e-4f

typedef unsigned long long ull;

// skewed column placement inside a row (ull units); 16B-aligned for all c
#define SKEW(c) (2*(c) + 2*((c) >> 3))

__constant__ float2 GW2[6] = {
    {0.00102838f, 0.00102838f},
    {0.00759876f, 0.00759876f},
    {0.03600077f, 0.03600077f},
    {0.10936069f, 0.10936069f},
    {0.21300554f, 0.21300554f},
    {0.26601172f, 0.26601172f}
};

__device__ ull g_acc[2] = {0ull, 0ull};
__device__ unsigned g_count = 0u;

static __device__ __forceinline__ ull fma2(ull a, ull b, ull c) {
    ull r; asm("fma.rn.f32x2 %0, %1, %2, %3;" : "=l"(r) : "l"(a), "l"(b), "l"(c));
    return r;
}
static __device__ __forceinline__ ull mul2(ull a, ull b) {
    ull r; asm("mul.rn.f32x2 %0, %1, %2;" : "=l"(r) : "l"(a), "l"(b));
    return r;
}
static __device__ __forceinline__ ull pack2(float lo, float hi) {
    ull r; asm("mov.b64 %0, {%1,%2};" : "=l"(r) : "f"(lo), "f"(hi));
    return r;
}
static __device__ __forceinline__ float2 unpack2(ull v) {
    float2 r; asm("mov.b64 {%0,%1}, %2;" : "=f"(r.x), "=f"(r.y) : "l"(v));
    return r;
}
static __device__ __forceinline__ float frcp(float a) {
    float r; asm("rcp.approx.ftz.f32 %0, %1;" : "=f"(r) : "f"(a));
    return r;
}

__global__ __launch_bounds__(256, 3)
void loss_kernel(const float* __restrict__ x, const float* __restrict__ y,
                 float* __restrict__ out)
{
    extern __shared__ ull h[];         // [LHBUF][HSTR], skewed columns
    __shared__ float red[16];
    __shared__ int  s_last;

    const int tid   = threadIdx.x;
    const int bx    = blockIdx.x;
    const int by    = blockIdx.y;
    const int plane = blockIdx.z;
    const int base  = bx * TW;
    const int r0    = by * TH - HALO;

    const float* __restrict__ xp = x + (size_t)plane * (IMG * IMG);
    const float* __restrict__ yp = y + (size_t)plane * (IMG * IMG);

    ull gw[6];
    #pragma unroll
    for (int k = 0; k < 6; k++) gw[k] = ((const ull*)GW2)[k];
    #define WK(k) gw[(k) <= 5 ? (k) : 10 - (k)]

    // ---- zero the 2 guard rows (96,97) ----
    if (tid < 2 * HSTR) h[LH * HSTR + tid] = 0ull;

    // ---- horizontal pass: 8 outputs/unit; 384 units = 256 + 128 ----
    ull mse2 = 0ull;                  // packed (junk, sum d^2)
    #pragma unroll
    for (int iter = 0; iter < 2; iter++) {
        if (iter == 1 && tid >= 128) break;   // warps 4-7 skip: warp-uniform
        const int u     = iter * 256 + tid;
        const int r     = u >> 2;
        const int q     = u & 3;
        const int gr    = r0 + r;
        const bool rowok = ((unsigned)gr < IMG);
        const int c0c   = base + 8 * q;
        const float* xrow = xp + gr * IMG;
        const float* yrow = yp + gr * IMG;

        float4 X[4], Y[4];
        #pragma unroll
        for (int m = 0; m < 4; m++) {
            const int col = c0c - 4 + 4 * m;
            const bool ok = rowok & ((unsigned)col < IMG);
            X[m] = ok ? __ldg((const float4*)(xrow + col)) : make_float4(0.f,0.f,0.f,0.f);
            Y[m] = ok ? __ldg((const float4*)(yrow + col)) : make_float4(0.f,0.f,0.f,0.f);
        }
        float ex = 0.f, ey = 0.f, fxe = 0.f, fye = 0.f;
        if (q == 0) {
            const int col = base - 8;
            if (rowok & (col >= 0)) {
                ex = __ldg((const float4*)(xrow + col)).w;
                ey = __ldg((const float4*)(yrow + col)).w;
            }
        }
        if (q == 3) {
            const int col = c0c + 12;
            if (rowok & ((unsigned)col < IMG)) {
                fxe = __ldg((const float4*)(xrow + col)).x;
                fye = __ldg((const float4*)(yrow + col)).x;
            }
        }

        ull w[18];
        #pragma unroll
        for (int m = 0; m < 4; m++) {
            const float* fxp = (const float*)&X[m];
            const float* fyp = (const float*)&Y[m];
            #pragma unroll
            for (int e = 0; e < 4; e++)
                w[1 + 4*m + e] = pack2(fxp[e] + fyp[e], fxp[e] - fyp[e]);
        }
        ull wl = __shfl_up_sync(0xffffffffu, w[8], 1);
        ull wr = __shfl_down_sync(0xffffffffu, w[9], 1);
        if (q == 0) wl = pack2(ex + ey, ex - ey);
        if (q == 3) wr = pack2(fxe + fye, fxe - fye);
        w[0]  = wl;
        w[17] = wr;

        // MSE: h row r maps to tile output row r-HALO; count once per band
        const bool mrowok = (r >= HALO) & (r < HALO + TH) & rowok &
                            (by * TH + r - HALO < IMG);

        ull a1[8] = {0,0,0,0,0,0,0,0};
        ull a2[8] = {0,0,0,0,0,0,0,0};
        #pragma unroll
        for (int t = 0; t < 18; t++) {
            ull v  = w[t];
            ull v2 = mul2(v, v);
            if (t >= 5 && t <= 12) {
                if (mrowok) mse2 = fma2(v, v, mse2);
            }
            #pragma unroll
            for (int o = 0; o < 8; o++) {
                const int k = t - o;
                if (k >= 0 && k <= 10) {
                    a1[o] = fma2(v,  WK(k), a1[o]);
                    a2[o] = fma2(v2, WK(k), a2[o]);
                }
            }
        }
        ull* hrow = h + r * HSTR;
        #pragma unroll
        for (int o = 0; o < 8; o++)
            *((ulonglong2*)(hrow + SKEW(8*q + o))) = make_ulonglong2(a1[o], a2[o]);
    }
    float mse_acc = unpack2(mse2).y;
    __syncthreads();

    // ---- vertical pass: 1 column x 11 consecutive rows per thread ----
    const int c  = tid & 31;
    const int rb = (tid >> 5) * 11;    // 0,11,...,77 (rows 86,87 masked)

    ull b1[11] = {0,0,0,0,0,0,0,0,0,0,0};
    ull b2[11] = {0,0,0,0,0,0,0,0,0,0,0};
    const ull* vp = h + rb * HSTR + SKEW(c);
    #pragma unroll
    for (int j = 0; j < 21; j++) {
        ulonglong2 u = *((const ulonglong2*)(vp + j * HSTR));
        #pragma unroll
        for (int o = 0; o < 11; o++) {
            const int k = j - o;
            if (k >= 0 && k <= 10) {
                b1[o] = fma2(u.x, WK(k), b1[o]);
                b2[o] = fma2(u.y, WK(k), b2[o]);
            }
        }
    }

    // ---- SSIM epilogue: batch 4 divisions per MUFU.RCP ----
    float ssim_acc = 0.f;
    float Nacc = 0.f, Dacc = 1.f;
    int   cnt = 0;
    #pragma unroll
    for (int o = 0; o < 11; o++) {
        const int tr  = rb + o;
        const int gro = by * TH + tr;
        if (tr < TH && gro < IMG) {
            float2 m = unpack2(b1[o]);   // (mu_s, mu_d)
            float2 e = unpack2(b2[o]);   // (E[s^2], E[d^2])
            float mus2 = m.x * m.x;
            float mud2 = m.y * m.y;
            float mu12   = 0.25f * (mus2 - mud2);
            float musum  = 0.5f  * (mus2 + mud2);
            float sig12  = 0.25f * (e.x - e.y) - mu12;
            float sigsum = 0.5f  * (e.x + e.y) - musum;
            float num = (2.f * mu12 + C1f) * (2.f * sig12 + C2f);
            float den = (musum + C1f) * (sigsum + C2f);
            Nacc = Nacc * den + num * Dacc;
            Dacc = Dacc * den;
            cnt++;
            if (cnt == 4) {
                ssim_acc = fmaf(Nacc, frcp(Dacc), ssim_acc);
                Nacc = 0.f; Dacc = 1.f; cnt = 0;
            }
        }
    }
    if (cnt > 0)
        ssim_acc = fmaf(Nacc, frcp(Dacc), ssim_acc);

    // ---- block reduction -> deterministic fixed-point atomics ----
    #pragma unroll
    for (int off = 16; off > 0; off >>= 1) {
        ssim_acc += __shfl_down_sync(0xffffffffu, ssim_acc, off);
        mse_acc  += __shfl_down_sync(0xffffffffu, mse_acc,  off);
    }
    if ((tid & 31) == 0) {
        red[tid >> 5]       = ssim_acc;
        red[8 + (tid >> 5)] = mse_acc;
    }
    __syncthreads();
    if (tid == 0) {
        float ss = 0.f, mm = 0.f;
        #pragma unroll
        for (int w2 = 0; w2 < 8; w2++) { ss += red[w2]; mm += red[8 + w2]; }
        atomicAdd(&g_acc[0], (ull)__double2ll_rn((double)ss * FXS));
        atomicAdd(&g_acc[1], (ull)__double2ll_rn((double)mm * FXS));
        __threadfence();
        unsigned t = atomicAdd(&g_count, 1u);
        s_last = (t == NBLOCKS - 1);
    }
    __syncthreads();

    // ---- last block finalizes and resets for next graph replay ----
    if (s_last && tid == 0) {
        __threadfence();
        ull a0  = atomicExch(&g_acc[0], 0ull);
        ull a1v = atomicExch(&g_acc[1], 0ull);
        atomicExch(&g_count, 0u);
        double inv = 1.0 / (NPIX * FXS);
        double ss = (double)(long long)a0 * inv;
        double mm = (double)(long long)a1v * inv;
        out[0] = (float)(1.0 - ss + mm);
    }
}

extern "C" void kernel_launch(void* const* d_in, const int* in_sizes, int n_in,
                              void* d_out, int out_size)
{
    const float* x = (const float*)d_in[0];
    const float* y = (const float*)d_in[1];
    float* out = (float*)d_out;

    cudaFuncSetAttribute(loss_kernel,
                         cudaFuncAttributeMaxDynamicSharedMemorySize, SMEMB);

    dim3 grid(NBX, NBY, NPL);   // (16, 6, 48) = 4608 blocks
    loss_kernel<<<grid, 256, SMEMB>>>(x, y, out);
}